// round 13
// baseline (speedup 1.0000x reference)
#include <cuda_runtime.h>
#include <cuda_bf16.h>
#include <cuda_fp16.h>
#include <math.h>
#include <cstdint>

// ---------------------------------------------------------------------------
// CSBrainLLMVQ. Exact fp32 path for everything feeding the output.
//   score[t,k] = 0.5*||cb_k||^2 - inp_b.cb_k - pe2[t].G[k],  G = cb @ inp_w
//   out[t]     = code_out[idx[t]] + outp_b,   code_out = cb @ outp_w.T
// VQ argmin:
//   phase1: mma.sync bf16 2-split -> approx scores (fp16) + rowmin atomics
//   phase2: single-pass candidates within MARGIN, exact fp32 sequential
//           rescore (R3-bit-identical chain) -> exact idx.
// R11: phase1 fragment loads via ldmatrix (LDS-bound -> tensor-bound),
//      fused DFT GEMM (re+im+mag one kernel, bit-identical chains),
//      cvtB fused into prep epilogue.
// ---------------------------------------------------------------------------

#define BB   32
#define CHN  19
#define NPP  30
#define PSZ  200
#define RR   570
#define TT   18240
#define TTP  18304            // 143*128
#define DMD  200
#define LLM  4096
#define KCB  4096
#define C25  25
#define W8   8
#define HTOT (BB*C25*RR*W8)
#define PETOT (TT*DMD)
#define NFREQ 101
#define KPAD 640
#define MARGIN 4e-3f

__device__ float g_bufA[HTOT];
__device__ float g_bufB[HTOT];
__device__ float g_pe[PETOT];
__device__ float g_spec[TT*NFREQ];
__device__ float g_ctab[PSZ*NFREQ];
__device__ float g_stab[PSZ*NFREQ];
__device__ float g_G[KCB*DMD];
__device__ float g_c0[KCB];
__device__ float g_cout[KCB*DMD];
__device__ int   g_idx[TT];
__device__ float g_mean[BB*5];
__device__ float g_rstd[BB*5];
__device__ __nv_bfloat16 g_A2[(size_t)TTP*KPAD];
__device__ __nv_bfloat16 g_B2[(size_t)KCB*KPAD];   // pad cols [600,640) stay 0
__device__ __half g_sap16[(size_t)TTP*KCB];
__device__ unsigned g_rowmin[TT];

__device__ __forceinline__ float gelu_exact(float v) {
    return 0.5f * v * (1.0f + erff(v * 0.70710678118654752f));
}

__device__ __forceinline__ uint32_t smem_to_u32(const void* p) {
    uint32_t a;
    asm("{ .reg .u64 t; cvta.to.shared.u64 t, %1; cvt.u32.u64 %0, t; }" : "=r"(a) : "l"(p));
    return a;
}

// order-preserving float <-> uint encode (for unsigned atomicMin)
__device__ __forceinline__ unsigned fenc(float f) {
    unsigned u = __float_as_uint(f);
    return (u & 0x80000000u) ? ~u : (u | 0x80000000u);
}
__device__ __forceinline__ float fdec(unsigned u) {
    unsigned b = (u & 0x80000000u) ? (u & 0x7FFFFFFFu) : ~u;
    return __uint_as_float(b);
}

#define PACKDUP(dst, a) \
    asm("mov.b64 %0, {%1, %1};" : "=l"(dst) : "r"(__float_as_uint(a)))
#define PACK2(dst, a, b) \
    asm("mov.b64 %0, {%1, %2};" : "=l"(dst) : "r"(__float_as_uint(a)), "r"(__float_as_uint(b)))
#define FMA2(acc, a, b) \
    asm("fma.rn.f32x2 %0, %1, %2, %0;" : "+l"(acc) : "l"(a), "l"(b))
#define UNPK2(lo, hi, v) \
    asm("mov.b64 {%0, %1}, %2;" : "=r"(lo), "=r"(hi) : "l"(v))

// ---------------------------------------------------------------------------
__global__ __launch_bounds__(256) void k_initmin() {
    int i = blockIdx.x * 256 + threadIdx.x;
    if (i < TT) g_rowmin[i] = 0xFFFFFFFFu;
}

// ---------------------------------------------------------------------------
// twiddle tables: ctab[n*NFREQ+f] = cosf(ang(m)), m=(n*f)%200 — bit-identical
// to the original twc[m]/tws[m] values.
// ---------------------------------------------------------------------------
__global__ __launch_bounds__(256) void k_twtab() {
    int i = blockIdx.x * 256 + threadIdx.x;
    if (i >= PSZ * NFREQ) return;
    int n = i / NFREQ, f = i % NFREQ;
    int m = (n * f) % PSZ;
    float ang = 6.283185307179586f * (float)m / 200.f;
    g_ctab[i] = cosf(ang);
    g_stab[i] = sinf(ang);
}

// ---------------------------------------------------------------------------
// fused DFT GEMM: re/im accumulated together (shared x tile), magnitude
// epilogue verbatim. Chains ascending-k -> bit-identical to prior rounds.
// M=TT (285x64 exact), N=101, K=200 (25x8 exact).
// ---------------------------------------------------------------------------
__global__ __launch_bounds__(256) void k_dftgemm(const float* __restrict__ x) {
    __shared__ __align__(16) float As[8][68];
    __shared__ __align__(16) float Cs[8][68];
    __shared__ __align__(16) float Ss[8][68];
    int m0 = blockIdx.y * 64, n0 = blockIdx.x * 64;
    int t = threadIdx.x;
    int tx = t % 16, ty = t / 16;
    float ar[4][4], ai[4][4];
    #pragma unroll
    for (int i = 0; i < 4; i++)
        #pragma unroll
        for (int j = 0; j < 4; j++) { ar[i][j] = 0.f; ai[i][j] = 0.f; }

    for (int kb = 0; kb < 25; kb++) {
        int k0 = kb * 8;
        {   // A: k-contiguous
            int kk = t & 7, mm = t >> 3;
            int k = k0 + kk;
            #pragma unroll
            for (int hh = 0; hh < 2; hh++) {
                int m = m0 + mm + hh * 32;
                As[kk][mm + hh * 32] = x[(size_t)m * PSZ + k];
            }
        }
        {   // tables: n-contiguous rows
            int nn = t & 63, kk4 = t >> 6;
            #pragma unroll
            for (int hh = 0; hh < 2; hh++) {
                int kk = kk4 + hh * 4;
                int k = k0 + kk, n = n0 + nn;
                bool ok = (n < NFREQ);
                Cs[kk][nn] = ok ? g_ctab[(size_t)k * NFREQ + n] : 0.f;
                Ss[kk][nn] = ok ? g_stab[(size_t)k * NFREQ + n] : 0.f;
            }
        }
        __syncthreads();
        #pragma unroll
        for (int kk = 0; kk < 8; kk++) {
            float4 av = *reinterpret_cast<const float4*>(&As[kk][ty * 4]);
            float4 cv = *reinterpret_cast<const float4*>(&Cs[kk][tx * 4]);
            float4 sv = *reinterpret_cast<const float4*>(&Ss[kk][tx * 4]);
            float a[4] = {av.x, av.y, av.z, av.w};
            float cb_[4] = {cv.x, cv.y, cv.z, cv.w};
            float sb_[4] = {sv.x, sv.y, sv.z, sv.w};
            #pragma unroll
            for (int i = 0; i < 4; i++)
                #pragma unroll
                for (int j = 0; j < 4; j++) {
                    ar[i][j] += a[i] * cb_[j];
                    ai[i][j] += a[i] * sb_[j];
                }
        }
        __syncthreads();
    }
    #pragma unroll
    for (int i = 0; i < 4; i++) {
        int m = m0 + ty * 4 + i;
        #pragma unroll
        for (int j = 0; j < 4; j++) {
            int n = n0 + tx * 4 + j;
            if (n < NFREQ) {
                float re = ar[i][j], im = ai[i][j];
                g_spec[(size_t)m * NFREQ + n] = sqrtf(re * re + im * im) * 0.005f;
            }
        }
    }
}

// ---------------------------------------------------------------------------
// conv1 (branch-free via zero-padded smem)
// ---------------------------------------------------------------------------
__global__ __launch_bounds__(256) void k_conv1(const float* __restrict__ x,
                                               const float* __restrict__ w,
                                               const float* __restrict__ bias) {
    int br = blockIdx.x;
    int b = br / RR, r = br % RR;
    __shared__ float xs[248];
    __shared__ float ws[C25 * 49];
    __shared__ float bs[C25];
    int t = threadIdx.x;
    if (t < 248) xs[t] = (t >= 24 && t < 224) ? x[(size_t)br * PSZ + t - 24] : 0.f;
    for (int i = t; i < C25 * 49; i += 256) ws[i] = w[i];
    if (t < C25) bs[t] = bias[t];
    __syncthreads();
    if (t < 200) {
        int oc = t >> 3, ow = t & 7;
        float acc = bs[oc];
        int base = ow * 25;
        #pragma unroll 7
        for (int k = 0; k < 49; k++)
            acc += xs[base + k] * ws[oc * 49 + k];
        g_bufA[(((size_t)b * C25 + oc) * RR + r) * W8 + ow] = acc;
    }
}

// ---------------------------------------------------------------------------
__global__ __launch_bounds__(256) void k_gnstats(const float* __restrict__ h) {
    int bg = blockIdx.x;
    int b = bg / 5, g = bg % 5;
    float s1 = 0.f, s2 = 0.f;
    const int per = RR * W8;
    for (int i = threadIdx.x; i < 5 * per; i += 256) {
        int oc = g * 5 + i / per;
        int rw = i % per;
        float v = h[(size_t)(b * C25 + oc) * per + rw];
        s1 += v; s2 += v * v;
    }
    __shared__ float r1[256], r2[256];
    int t = threadIdx.x;
    r1[t] = s1; r2[t] = s2;
    __syncthreads();
    for (int s = 128; s > 0; s >>= 1) {
        if (t < s) { r1[t] += r1[t + s]; r2[t] += r2[t + s]; }
        __syncthreads();
    }
    if (t == 0) {
        float m = r1[0] / 22800.f;
        float var = r2[0] / 22800.f - m * m;
        g_mean[bg] = m;
        g_rstd[bg] = rsqrtf(var + 1e-5f);
    }
}

// ---------------------------------------------------------------------------
__global__ __launch_bounds__(256) void k_conv3x(const float* __restrict__ in,
                                                const float* __restrict__ w,
                                                const float* __restrict__ bias,
                                                const float* __restrict__ gns,
                                                const float* __restrict__ gnb,
                                                float* __restrict__ out) {
    int bi = blockIdx.x;
    int b = bi / 72, rt = bi % 72;
    int r0 = rt * 8;
    int nrows = min(8, RR - r0);
    __shared__ float sIn[C25][8][W8];
    __shared__ float sW[C25 * C25 * 3];
    __shared__ float sB[C25];
    __shared__ float sMean[C25], sRstd[C25], sSc[C25], sBi[C25];
    int t = threadIdx.x;
    for (int i = t; i < C25 * C25 * 3; i += 256) sW[i] = w[i];
    if (t < C25) {
        sB[t] = bias[t];
        int bg = b * 5 + t / 5;
        sMean[t] = g_mean[bg];
        sRstd[t] = g_rstd[bg];
        sSc[t]   = gns[t];
        sBi[t]   = gnb[t];
    }
    for (int i = t; i < C25 * nrows * W8; i += 256) {
        int ic = i / (nrows * W8);
        int lr = (i / W8) % nrows;
        int ww = i & 7;
        sIn[ic][lr][ww] = in[(((size_t)b * C25 + ic) * RR + r0 + lr) * W8 + ww];
    }
    __syncthreads();
    for (int i = t; i < C25 * nrows * W8; i += 256) {
        int ic = i / (nrows * W8);
        int lr = (i / W8) % nrows;
        int ww = i & 7;
        float v = (sIn[ic][lr][ww] - sMean[ic]) * sRstd[ic] * sSc[ic] + sBi[ic];
        sIn[ic][lr][ww] = gelu_exact(v);
    }
    __syncthreads();
    if (t < 200) {
        int oc = t >> 3, ww = t & 7;
        for (int lr = 0; lr < nrows; lr++) {
            float acc = sB[oc];
            #pragma unroll
            for (int ic = 0; ic < C25; ic++) {
                const float* wp = &sW[(oc * C25 + ic) * 3];
                if (ww > 0) acc += sIn[ic][lr][ww - 1] * wp[0];
                acc += sIn[ic][lr][ww] * wp[1];
                if (ww < 7) acc += sIn[ic][lr][ww + 1] * wp[2];
            }
            out[(((size_t)b * C25 + oc) * RR + r0 + lr) * W8 + ww] = acc;
        }
    }
}

// ---------------------------------------------------------------------------
__global__ __launch_bounds__(256) void k_mkpe(const float* __restrict__ gns,
                                              const float* __restrict__ gnb,
                                              const float* __restrict__ spec_b) {
    int i = blockIdx.x * 256 + threadIdx.x;
    if (i >= PETOT) return;
    int tkn = i / DMD, d = i % DMD;
    int b = tkn / RR, r = tkn % RR;
    int ic = d >> 3;
    int bg = b * 5 + ic / 5;
    float raw = g_bufA[(((size_t)b * C25 + ic) * RR + r) * W8 + (d & 7)];
    float v = (raw - g_mean[bg]) * g_rstd[bg] * gns[ic] + gnb[ic];
    g_pe[i] = gelu_exact(v) + spec_b[d];
}

// ---------------------------------------------------------------------------
// generic fp32 SGEMM (spectral projection): C += A @ B
// ---------------------------------------------------------------------------
__global__ __launch_bounds__(256) void k_sgemm(const float* __restrict__ A,
                                               const float* __restrict__ Bm,
                                               float* __restrict__ C,
                                               int M, int N, int K,
                                               int lda, int bk, int bn, int ldc,
                                               int accFlag) {
    __shared__ __align__(16) float As[8][68];
    __shared__ __align__(16) float Bs[8][68];
    int m0 = blockIdx.y * 64, n0 = blockIdx.x * 64;
    int t = threadIdx.x;
    int tx = t % 16, ty = t / 16;
    float acc[4][4];
    #pragma unroll
    for (int i = 0; i < 4; i++)
        #pragma unroll
        for (int j = 0; j < 4; j++) acc[i][j] = 0.f;

    int nk = (K + 7) / 8;
    for (int kb = 0; kb < nk; kb++) {
        int k0 = kb * 8;
        {
            int kk = t & 7, mm = t >> 3;
            int k = k0 + kk;
            #pragma unroll
            for (int hh = 0; hh < 2; hh++) {
                int m = m0 + mm + hh * 32;
                As[kk][mm + hh * 32] = (k < K && m < M) ? A[(size_t)m * lda + k] : 0.f;
            }
        }
        {
            int kk = t & 7, nn = t >> 3;
            int k = k0 + kk;
            #pragma unroll
            for (int hh = 0; hh < 2; hh++) {
                int n = n0 + nn + hh * 32;
                Bs[kk][nn + hh * 32] = (k < K && n < N) ? Bm[(size_t)k * bk + (size_t)n * bn] : 0.f;
            }
        }
        __syncthreads();
        #pragma unroll
        for (int kk = 0; kk < 8; kk++) {
            float4 av = *reinterpret_cast<const float4*>(&As[kk][ty * 4]);
            float4 bv = *reinterpret_cast<const float4*>(&Bs[kk][tx * 4]);
            float a[4] = {av.x, av.y, av.z, av.w};
            float bb[4] = {bv.x, bv.y, bv.z, bv.w};
            #pragma unroll
            for (int i = 0; i < 4; i++)
                #pragma unroll
                for (int j = 0; j < 4; j++) acc[i][j] += a[i] * bb[j];
        }
        __syncthreads();
    }
    #pragma unroll
    for (int i = 0; i < 4; i++) {
        int m = m0 + ty * 4 + i;
        if (m >= M) continue;
        #pragma unroll
        for (int j = 0; j < 4; j++) {
            int n = n0 + tx * 4 + j;
            if (n < N) {
                size_t o = (size_t)m * ldc + n;
                C[o] = accFlag ? (C[o] + acc[i][j]) : acc[i][j];
            }
        }
    }
}

// ---------------------------------------------------------------------------
__global__ __launch_bounds__(256) void k_c0(const float* __restrict__ cb,
                                            const float* __restrict__ inp_b) {
    int k = blockIdx.x;
    float s = 0.f, sb = 0.f;
    for (int l = threadIdx.x; l < LLM; l += 256) {
        float v = cb[(size_t)k * LLM + l];
        s += v * v;
        sb += inp_b[l] * v;
    }
    __shared__ float r1[256], r2[256];
    int t = threadIdx.x;
    r1[t] = s; r2[t] = sb;
    __syncthreads();
    for (int st = 128; st > 0; st >>= 1) {
        if (t < st) { r1[t] += r1[t + st]; r2[t] += r2[t + st]; }
        __syncthreads();
    }
    if (t == 0) g_c0[k] = 0.5f * r1[0] - r2[0];
}

// ---------------------------------------------------------------------------
// k_prep (R3-identical math) + fused cvtB: writes G, cout, AND g_B2 splits
// directly from register-resident G values.
// ---------------------------------------------------------------------------
__global__ __launch_bounds__(256) void k_prep(const float* __restrict__ cb,
                                              const float* __restrict__ inp_w,
                                              const float* __restrict__ outp_w) {
    __shared__ __align__(16) float As[2][8][68];
    __shared__ __align__(16) float B1s[2][8][68];
    __shared__ __align__(16) float B2s[2][8][68];
    const int t = threadIdx.x;
    const int tx = t & 15, ty = t >> 4;
    const int lk = t & 7, lm = t >> 3;
    const int nn = t & 63, kq = t >> 6;
    const int m0 = blockIdx.y * 64, n0 = blockIdx.x * 64;

    unsigned long long a1[4][2], a2[4][2];
    #pragma unroll
    for (int i = 0; i < 4; i++)
        #pragma unroll
        for (int jp = 0; jp < 2; jp++) { a1[i][jp] = 0ULL; a2[i][jp] = 0ULL; }

    #pragma unroll
    for (int h = 0; h < 2; h++) {
        As[0][lk][lm + h * 32] = cb[(size_t)(m0 + lm + h * 32) * LLM + lk];
        int kk = kq + h * 4;
        B1s[0][kk][nn] = (n0 + nn < DMD) ? inp_w[(size_t)kk * DMD + n0 + nn] : 0.f;
        B2s[0][lk][lm + h * 32] = (n0 + lm + h * 32 < DMD)
            ? outp_w[(size_t)(n0 + lm + h * 32) * LLM + lk] : 0.f;
    }
    __syncthreads();
    for (int kb = 0; kb < LLM / 8; kb++) {
        int cur = kb & 1, nxt = cur ^ 1;
        if (kb < LLM / 8 - 1) {
            int k0 = (kb + 1) * 8;
            #pragma unroll
            for (int h = 0; h < 2; h++) {
                As[nxt][lk][lm + h * 32] = cb[(size_t)(m0 + lm + h * 32) * LLM + k0 + lk];
                int kk = kq + h * 4;
                B1s[nxt][kk][nn] = (n0 + nn < DMD) ? inp_w[(size_t)(k0 + kk) * DMD + n0 + nn] : 0.f;
                B2s[nxt][lk][lm + h * 32] = (n0 + lm + h * 32 < DMD)
                    ? outp_w[(size_t)(n0 + lm + h * 32) * LLM + k0 + lk] : 0.f;
            }
        }
        #pragma unroll
        for (int kk = 0; kk < 8; kk++) {
            float4 av = *reinterpret_cast<const float4*>(&As[cur][kk][ty * 4]);
            float4 b1 = *reinterpret_cast<const float4*>(&B1s[cur][kk][tx * 4]);
            float4 b2 = *reinterpret_cast<const float4*>(&B2s[cur][kk][tx * 4]);
            unsigned long long b1p[2], b2p[2];
            PACK2(b1p[0], b1.x, b1.y); PACK2(b1p[1], b1.z, b1.w);
            PACK2(b2p[0], b2.x, b2.y); PACK2(b2p[1], b2.z, b2.w);
            float aa[4] = {av.x, av.y, av.z, av.w};
            #pragma unroll
            for (int i = 0; i < 4; i++) {
                unsigned long long ap;
                PACKDUP(ap, aa[i]);
                FMA2(a1[i][0], ap, b1p[0]);
                FMA2(a1[i][1], ap, b1p[1]);
                FMA2(a2[i][0], ap, b2p[0]);
                FMA2(a2[i][1], ap, b2p[1]);
            }
        }
        __syncthreads();
    }
    #pragma unroll
    for (int i = 0; i < 4; i++) {
        int m = m0 + ty * 4 + i;
        #pragma unroll
        for (int jp = 0; jp < 2; jp++) {
            unsigned lo, hi;
            int n = n0 + tx * 4 + jp * 2;
            UNPK2(lo, hi, a1[i][jp]);
            #pragma unroll
            for (int half = 0; half < 2; half++) {
                int nc = n + half;
                if (nc < DMD) {
                    float v = __uint_as_float(half ? hi : lo);
                    g_G[(size_t)m * DMD + nc] = v;
                    __nv_bfloat16 vh = __float2bfloat16(v);
                    __nv_bfloat16 vl = __float2bfloat16(v - __bfloat162float(vh));
                    g_B2[(size_t)m * KPAD + nc]       = vh;
                    g_B2[(size_t)m * KPAD + 400 + nc] = vh;
                    g_B2[(size_t)m * KPAD + 200 + nc] = vl;
                }
            }
            UNPK2(lo, hi, a2[i][jp]);
            if (n < DMD)     g_cout[(size_t)m * DMD + n]     = __uint_as_float(lo);
            if (n + 1 < DMD) g_cout[(size_t)m * DMD + n + 1] = __uint_as_float(hi);
        }
    }
}

// ---------------------------------------------------------------------------
__global__ __launch_bounds__(256) void k_pos(const float* __restrict__ pw,
                                             const float* __restrict__ pb) {
    int b = blockIdx.x / DMD, d = blockIdx.x % DMD;
    __shared__ float mp[RR];
    __shared__ float w[133];
    int t = threadIdx.x;
    for (int i = t; i < RR; i += 256)
        mp[i] = g_pe[((size_t)b * RR + i) * DMD + d];
    if (t < 133) w[t] = pw[d * 133 + t];
    __syncthreads();
    float bias = pb[d];
    for (int o = t; o < RR; o += 256) {
        int ch = o / NPP, pn = o % NPP;
        float acc = mp[o] + bias;
        #pragma unroll
        for (int i = 0; i < 19; i++) {
            int ci = ch + i - 9;
            if (ci < 0 || ci >= CHN) continue;
            int base = ci * NPP;
            #pragma unroll
            for (int j = 0; j < 7; j++) {
                int pj = pn + j - 3;
                if (pj < 0 || pj >= NPP) continue;
                acc += mp[base + pj] * w[i * 7 + j];
            }
        }
        g_bufA[((size_t)b * RR + o) * DMD + d] = acc;
    }
}

// ---------------------------------------------------------------------------
// bf16 2-split conversion for A: A' = [P_hi | P_hi | P_lo]
// ---------------------------------------------------------------------------
__global__ __launch_bounds__(256) void k_cvtA() {
    size_t i = (size_t)blockIdx.x * 256 + threadIdx.x;
    if (i >= (size_t)TTP * KPAD) return;
    int t = (int)(i / KPAD), c = (int)(i % KPAD);
    __nv_bfloat16 v = __float2bfloat16(0.f);
    if (t < TT && c < 600) {
        int d = (c < 200) ? c : (c < 400 ? c - 200 : c - 400);
        float x = g_bufA[(size_t)t * DMD + d];
        __nv_bfloat16 h = __float2bfloat16(x);
        if (c < 400) v = h;
        else         v = __float2bfloat16(x - __bfloat162float(h));
    }
    g_A2[i] = v;
}

// ---------------------------------------------------------------------------
// phase1: approx scores via mma.sync m16n8k16 bf16->fp32, ldmatrix fragment
// loads, register-prefetch pipeline, fp16 store + rowmin atomics.
// ---------------------------------------------------------------------------
#define SK 72

__device__ __forceinline__ void mma_bf16(float* c, uint32_t a0, uint32_t a1,
                                         uint32_t a2, uint32_t a3,
                                         uint32_t b0, uint32_t b1) {
    asm volatile(
        "mma.sync.aligned.m16n8k16.row.col.f32.bf16.bf16.f32 "
        "{%0,%1,%2,%3}, {%4,%5,%6,%7}, {%8,%9}, {%0,%1,%2,%3};"
        : "+f"(c[0]), "+f"(c[1]), "+f"(c[2]), "+f"(c[3])
        : "r"(a0), "r"(a1), "r"(a2), "r"(a3), "r"(b0), "r"(b1));
}

__device__ __forceinline__ void ldsm4(uint32_t& r0, uint32_t& r1,
                                      uint32_t& r2, uint32_t& r3, uint32_t addr) {
    asm volatile("ldmatrix.sync.aligned.m8n8.x4.shared.b16 {%0,%1,%2,%3}, [%4];"
        : "=r"(r0), "=r"(r1), "=r"(r2), "=r"(r3) : "r"(addr));
}

__global__ __launch_bounds__(256) void k_phase1() {
    __shared__ __nv_bfloat16 As[128][SK];
    __shared__ __nv_bfloat16 Bs[128][SK];
    __shared__ unsigned urmin[128];
    const int t = threadIdx.x, wid = t >> 5, lane = t & 31;
    const int m0 = blockIdx.x * 128, n0 = blockIdx.y * 128;
    const int wm = wid >> 2, wn = wid & 3;
    const int r = lane >> 2, cc = (lane & 3) * 2;
    const int lrow = t >> 3, lq = t & 7;

    if (t < 128) urmin[t] = 0xFFFFFFFFu;

    // ldmatrix lane addressing
    const int lj = lane >> 3, ri = lane & 7;
    const uint32_t aBase = smem_to_u32(&As[0][0]);
    const uint32_t bBase = smem_to_u32(&Bs[0][0]);
    uint32_t aAddr[4], bAddr[2];
    #pragma unroll
    for (int mt = 0; mt < 4; mt++)
        aAddr[mt] = aBase + (uint32_t)(((wm * 64 + mt * 16 + (lj & 1) * 8 + ri) * SK
                                        + (lj >> 1) * 8) * 2);
    #pragma unroll
    for (int p = 0; p < 2; p++)
        bAddr[p] = bBase + (uint32_t)(((wn * 32 + p * 16 + (lj >> 1) * 8 + ri) * SK
                                       + (lj & 1) * 8) * 2);

    float acc[4][4][4];
    #pragma unroll
    for (int mt = 0; mt < 4; mt++)
        #pragma unroll
        for (int nt = 0; nt < 4; nt++)
            #pragma unroll
            for (int q = 0; q < 4; q++) acc[mt][nt][q] = 0.f;

    float4 pa[4], pb[4];
    #pragma unroll
    for (int s = 0; s < 4; s++) {
        int row = lrow + s * 32;
        pa[s] = *reinterpret_cast<const float4*>(g_A2 + (size_t)(m0 + row) * KPAD + lq * 8);
        pb[s] = *reinterpret_cast<const float4*>(g_B2 + (size_t)(n0 + row) * KPAD + lq * 8);
    }

    for (int ch = 0; ch < 10; ch++) {
        #pragma unroll
        for (int s = 0; s < 4; s++) {
            int row = lrow + s * 32;
            *reinterpret_cast<float4*>(&As[row][lq * 8]) = pa[s];
            *reinterpret_cast<float4*>(&Bs[row][lq * 8]) = pb[s];
        }
        __syncthreads();
        if (ch < 9) {
            #pragma unroll
            for (int s = 0; s < 4; s++) {
                int row = lrow + s * 32;
                pa[s] = *reinterpret_cast<const float4*>(
                    g_A2 + (size_t)(m0 + row) * KPAD + (ch + 1) * 64 + lq * 8);
                pb[s] = *reinterpret_cast<const float4*>(
                    g_B2 + (size_t)(n0 + row) * KPAD + (ch + 1) * 64 + lq * 8);
            }
        }
        #pragma unroll
        for (int ks = 0; ks < 4; ks++) {
            const uint32_t koff = (uint32_t)(ks * 16 * 2);
            uint32_t a[4][4], b[4][2];
            #pragma unroll
            for (int mt = 0; mt < 4; mt++)
                ldsm4(a[mt][0], a[mt][1], a[mt][2], a[mt][3], aAddr[mt] + koff);
            #pragma unroll
            for (int p = 0; p < 2; p++)
                ldsm4(b[2 * p][0], b[2 * p][1], b[2 * p + 1][0], b[2 * p + 1][1],
                      bAddr[p] + koff);
            #pragma unroll
            for (int mt = 0; mt < 4; mt++)
                #pragma unroll
                for (int nt = 0; nt < 4; nt++)
                    mma_bf16(acc[mt][nt], a[mt][0], a[mt][1], a[mt][2], a[mt][3],
                             b[nt][0], b[nt][1]);
        }
        __syncthreads();
    }

    #pragma unroll
    for (int mt = 0; mt < 4; mt++) {
        int lr0 = wm * 64 + mt * 16 + r;
        float mlo = INFINITY, mhi = INFINITY;
        #pragma unroll
        for (int nt = 0; nt < 4; nt++) {
            int col = n0 + wn * 32 + nt * 8 + cc;
            float c0a = g_c0[col], c0b = g_c0[col + 1];
            float s0 = c0a - acc[mt][nt][0], s1 = c0b - acc[mt][nt][1];
            float s2 = c0a - acc[mt][nt][2], s3 = c0b - acc[mt][nt][3];
            mlo = fminf(mlo, fminf(s0, s1));
            mhi = fminf(mhi, fminf(s2, s3));
            int row0 = m0 + lr0;
            if (row0 < TT)
                *reinterpret_cast<__half2*>(&g_sap16[(size_t)row0 * KCB + col]) =
                    __floats2half2_rn(s0, s1);
            if (row0 + 8 < TT)
                *reinterpret_cast<__half2*>(&g_sap16[(size_t)(row0 + 8) * KCB + col]) =
                    __floats2half2_rn(s2, s3);
        }
        atomicMin(&urmin[lr0], fenc(mlo));
        atomicMin(&urmin[lr0 + 8], fenc(mhi));
    }
    __syncthreads();
    if (t < 128 && m0 + t < TT)
        atomicMin(&g_rowmin[m0 + t], urmin[t]);
}

// ---------------------------------------------------------------------------
// phase2: per-token (one warp): thr from g_rowmin, single candidate pass
// over fp16 scores, EXACT fp32 sequential rescore -> first-min idx.
// ---------------------------------------------------------------------------
__global__ __launch_bounds__(256) void k_select() {
    __shared__ int lists[8][64];
    int wid = threadIdx.x >> 5, lid = threadIdx.x & 31;
    int tt = blockIdx.x * 8 + wid;
    if (tt >= TT) return;
    const __half2* __restrict__ srow =
        reinterpret_cast<const __half2*>(g_sap16 + (size_t)tt * KCB);
    float thr = fdec(g_rowmin[tt]) + MARGIN;

    int cnt = 0;
    for (int j = 0; j < 64; j++) {
        int p = j * 32 + lid;
        __half2 h2 = srow[p];
        bool c0 = (__low2float(h2) <= thr);
        bool c1 = (__high2float(h2) <= thr);
        unsigned m0 = __ballot_sync(0xFFFFFFFFu, c0);
        if (c0) {
            int pos = cnt + __popc(m0 & ((1u << lid) - 1u));
            if (pos < 64) lists[wid][pos] = 2 * p;
        }
        cnt += __popc(m0);
        unsigned m1 = __ballot_sync(0xFFFFFFFFu, c1);
        if (c1) {
            int pos = cnt + __popc(m1 & ((1u << lid) - 1u));
            if (pos < 64) lists[wid][pos] = 2 * p + 1;
        }
        cnt += __popc(m1);
    }
    __syncwarp();

    const float* __restrict__ pe = g_bufA + (size_t)tt * DMD;
    float bv = INFINITY; int bk = 0;
    if (cnt <= 64) {
        for (int c = lid; c < cnt; c += 32) {
            int k = lists[wid][c];
            const float* gr = g_G + (size_t)k * DMD;
            float acc = 0.f;
            #pragma unroll 1
            for (int q = 0; q < DMD; q++) acc = fmaf(pe[q], gr[q], acc);
            float s = g_c0[k] - acc;
            if (s < bv || (s == bv && k < bk)) { bv = s; bk = k; }
        }
    } else {
        for (int k = lid; k < KCB; k += 32) {
            const float* gr = g_G + (size_t)k * DMD;
            float acc = 0.f;
            #pragma unroll 1
            for (int q = 0; q < DMD; q++) acc = fmaf(pe[q], gr[q], acc);
            float s = g_c0[k] - acc;
            if (s < bv || (s == bv && k < bk)) { bv = s; bk = k; }
        }
    }
    for (int o = 16; o; o >>= 1) {
        float ov = __shfl_xor_sync(0xFFFFFFFFu, bv, o);
        int ok = __shfl_xor_sync(0xFFFFFFFFu, bk, o);
        if (ov < bv || (ov == bv && ok < bk)) { bv = ov; bk = ok; }
    }
    if (lid == 0) g_idx[tt] = bk;
}

// ---------------------------------------------------------------------------
__global__ __launch_bounds__(256) void k_gather(const float* __restrict__ outp_b,
                                                float* __restrict__ out) {
    int i = blockIdx.x * 256 + threadIdx.x;
    if (i >= PETOT) return;
    int tkn = i / DMD, d = i % DMD;
    out[i] = g_cout[(size_t)g_idx[tkn] * DMD + d] + outp_b[d];
}

// ---------------------------------------------------------------------------
extern "C" void kernel_launch(void* const* d_in, const int* in_sizes, int n_in,
                              void* d_out, int out_size) {
    const float* x      = (const float*)d_in[0];
    const float* c1w    = (const float*)d_in[1];
    const float* c1b    = (const float*)d_in[2];
    const float* gn1s   = (const float*)d_in[3];
    const float* gn1b   = (const float*)d_in[4];
    const float* c2w    = (const float*)d_in[5];
    const float* c2b    = (const float*)d_in[6];
    const float* gn2s   = (const float*)d_in[7];
    const float* gn2b   = (const float*)d_in[8];
    const float* c3w    = (const float*)d_in[9];
    const float* c3b    = (const float*)d_in[10];
    const float* gn3s   = (const float*)d_in[11];
    const float* gn3b   = (const float*)d_in[12];
    const float* spec_w = (const float*)d_in[13];
    const float* spec_b = (const float*)d_in[14];
    const float* pos_w  = (const float*)d_in[15];
    const float* pos_b  = (const float*)d_in[16];
    const float* inp_w  = (const float*)d_in[17];
    const float* inp_b  = (const float*)d_in[18];
    const float* cb     = (const float*)d_in[19];
    const float* outp_w = (const float*)d_in[20];
    const float* outp_b = (const float*)d_in[21];
    float* out = (float*)d_out;

    static cudaStream_t s2 = nullptr, s3 = nullptr;
    static cudaEvent_t evFork = nullptr, evJoin = nullptr, evDft = nullptr;
    if (s2 == nullptr) {
        cudaStreamCreateWithFlags(&s2, cudaStreamNonBlocking);
        cudaStreamCreateWithFlags(&s3, cudaStreamNonBlocking);
        cudaEventCreateWithFlags(&evFork, cudaEventDisableTiming);
        cudaEventCreateWithFlags(&evJoin, cudaEventDisableTiming);
        cudaEventCreateWithFlags(&evDft,  cudaEventDisableTiming);
    }

    float *pSpec, *pBufA, *pBufB, *pPe;
    cudaGetSymbolAddress((void**)&pSpec, g_spec);
    cudaGetSymbolAddress((void**)&pBufA, g_bufA);
    cudaGetSymbolAddress((void**)&pBufB, g_bufB);
    cudaGetSymbolAddress((void**)&pPe,   g_pe);

    const int EW = (HTOT + 255) / 256;

    // ---- fork ----
    cudaEventRecord(evFork, 0);
    cudaStreamWaitEvent(s2, evFork, 0);
    cudaStreamWaitEvent(s3, evFork, 0);

    // s2: codebook branch (prep writes G, cout AND B2 splits; then c0)
    k_prep<<<dim3(4, 64), 256, 0, s2>>>(cb, inp_w, outp_w);
    k_c0<<<KCB, 256, 0, s2>>>(cb, inp_b);

    // s3: spectral DFT (table + fused re/im/mag GEMM)
    k_twtab<<<(PSZ * NFREQ + 255) / 256, 256, 0, s3>>>();
    k_dftgemm<<<dim3(2, TT / 64), 256, 0, s3>>>(x);
    cudaEventRecord(evDft, s3);

    // main: conv chain
    k_initmin<<<(TT + 255) / 256, 256>>>();
    k_conv1<<<TT, 256>>>(x, c1w, c1b);
    k_gnstats<<<BB * 5, 256>>>(pBufA);
    k_conv3x<<<BB * 72, 256>>>(pBufA, c2w, c2b, gn1s, gn1b, pBufB);
    k_gnstats<<<BB * 5, 256>>>(pBufB);
    k_conv3x<<<BB * 72, 256>>>(pBufB, c3w, c3b, gn2s, gn2b, pBufA);
    k_gnstats<<<BB * 5, 256>>>(pBufA);
    k_mkpe<<<EW, 256>>>(gn3s, gn3b, spec_b);
    cudaStreamWaitEvent(0, evDft, 0);
    k_sgemm<<<dim3((DMD + 63) / 64, TT / 64), 256>>>(pSpec, spec_w, pPe,
        TT, DMD, NFREQ, NFREQ, 1, NFREQ, DMD, 1);
    k_pos<<<BB * DMD, 256>>>(pos_w, pos_b);
    k_cvtA<<<(int)(((size_t)TTP * KPAD + 255) / 256), 256>>>();

    // ---- join with s2 ----
    cudaEventRecord(evJoin, s2);
    cudaStreamWaitEvent(0, evJoin, 0);

    k_phase1<<<dim3(TTP / 128, KCB / 128), 256>>>();
    k_select<<<(TT + 7) / 8, 256>>>();
    k_gather<<<EW, 256>>>(outp_b, out);
}

// round 16
// speedup vs baseline: 1.1466x; 1.1466x over previous
#include <cuda_runtime.h>
#include <cuda_bf16.h>
#include <cuda_fp16.h>
#include <math.h>
#include <cstdint>

// ---------------------------------------------------------------------------
// CSBrainLLMVQ. Exact fp32 path for everything feeding the output.
//   score[t,k] = 0.5*||cb_k||^2 - inp_b.cb_k - pe2[t].G[k],  G = cb @ inp_w
//   out[t]     = code_out[idx[t]] + outp_b,   code_out = cb @ outp_w.T
// VQ argmin:
//   phase1: SINGLE-panel bf16 mma.sync (K'=256) -> approx scores (fp16)
//           + fp32 rowmin atomics.
//   phase2: candidates within a COMPUTED rigorous bound
//           thr = rowmin + 2*Cb*||p_t||*Gmax + 6e-4|rowmin| + 1e-3,
//           Cb = 4.2e-3 >= bf16-rn dot error coeff (Cauchy-Schwarz),
//           then EXACT fp32 sequential rescore (R3-bit-identical chain)
//           -> idx provably exact.
// ---------------------------------------------------------------------------

#define BB   32
#define CHN  19
#define NPP  30
#define PSZ  200
#define RR   570
#define TT   18240
#define TTP  18304            // 143*128
#define DMD  200
#define LLM  4096
#define KCB  4096
#define C25  25
#define W8   8
#define HTOT (BB*C25*RR*W8)
#define PETOT (TT*DMD)
#define NFREQ 101
#define KPAD 256              // hi panel only: cols [0,200) data, [200,256) zero
#define NCH  4                // KPAD/64

__device__ float g_bufA[HTOT];
__device__ float g_bufB[HTOT];
__device__ float g_pe[PETOT];
__device__ float g_spec[TT*NFREQ];
__device__ float g_ctab[PSZ*NFREQ];
__device__ float g_stab[PSZ*NFREQ];
__device__ float g_G[KCB*DMD];
__device__ float g_c0[KCB];
__device__ float g_cout[KCB*DMD];
__device__ int   g_idx[TT];
__device__ float g_mean[BB*5];
__device__ float g_rstd[BB*5];
__device__ __nv_bfloat16 g_A2[(size_t)TTP*KPAD];
__device__ __nv_bfloat16 g_B2[(size_t)KCB*KPAD];   // pad cols stay 0
__device__ __half g_sap16[(size_t)TTP*KCB];
__device__ unsigned g_rowmin[TT];
__device__ float g_pn[TT];
__device__ unsigned g_gmaxu;    // max_k ||G_k||2, as positive-float bits

__device__ __forceinline__ float gelu_exact(float v) {
    return 0.5f * v * (1.0f + erff(v * 0.70710678118654752f));
}

__device__ __forceinline__ uint32_t smem_to_u32(const void* p) {
    uint32_t a;
    asm("{ .reg .u64 t; cvta.to.shared.u64 t, %1; cvt.u32.u64 %0, t; }" : "=r"(a) : "l"(p));
    return a;
}

// order-preserving float <-> uint encode (for unsigned atomicMin)
__device__ __forceinline__ unsigned fenc(float f) {
    unsigned u = __float_as_uint(f);
    return (u & 0x80000000u) ? ~u : (u | 0x80000000u);
}
__device__ __forceinline__ float fdec(unsigned u) {
    unsigned b = (u & 0x80000000u) ? (u & 0x7FFFFFFFu) : ~u;
    return __uint_as_float(b);
}

#define PACKDUP(dst, a) \
    asm("mov.b64 %0, {%1, %1};" : "=l"(dst) : "r"(__float_as_uint(a)))
#define PACK2(dst, a, b) \
    asm("mov.b64 %0, {%1, %2};" : "=l"(dst) : "r"(__float_as_uint(a)), "r"(__float_as_uint(b)))
#define FMA2(acc, a, b) \
    asm("fma.rn.f32x2 %0, %1, %2, %0;" : "+l"(acc) : "l"(a), "l"(b))
#define UNPK2(lo, hi, v) \
    asm("mov.b64 {%0, %1}, %2;" : "=r"(lo), "=r"(hi) : "l"(v))

// ---------------------------------------------------------------------------
__global__ __launch_bounds__(256) void k_initmin() {
    int i = blockIdx.x * 256 + threadIdx.x;
    if (i < TT) g_rowmin[i] = 0xFFFFFFFFu;
}

// ---------------------------------------------------------------------------
// twiddle tables (bit-identical to the original twc/tws values)
// ---------------------------------------------------------------------------
__global__ __launch_bounds__(256) void k_twtab() {
    int i = blockIdx.x * 256 + threadIdx.x;
    if (i >= PSZ * NFREQ) return;
    int n = i / NFREQ, f = i % NFREQ;
    int m = (n * f) % PSZ;
    float ang = 6.283185307179586f * (float)m / 200.f;
    g_ctab[i] = cosf(ang);
    g_stab[i] = sinf(ang);
}

// ---------------------------------------------------------------------------
// fused DFT GEMM (re+im+mag), ascending-k chains -> g_spec bit-identical.
// ---------------------------------------------------------------------------
__global__ __launch_bounds__(256) void k_dftgemm(const float* __restrict__ x) {
    __shared__ __align__(16) float As[8][68];
    __shared__ __align__(16) float Cs[8][68];
    __shared__ __align__(16) float Ss[8][68];
    int m0 = blockIdx.y * 64, n0 = blockIdx.x * 64;
    int t = threadIdx.x;
    int tx = t % 16, ty = t / 16;
    float ar[4][4], ai[4][4];
    #pragma unroll
    for (int i = 0; i < 4; i++)
        #pragma unroll
        for (int j = 0; j < 4; j++) { ar[i][j] = 0.f; ai[i][j] = 0.f; }

    for (int kb = 0; kb < 25; kb++) {
        int k0 = kb * 8;
        {
            int kk = t & 7, mm = t >> 3;
            int k = k0 + kk;
            #pragma unroll
            for (int hh = 0; hh < 2; hh++) {
                int m = m0 + mm + hh * 32;
                As[kk][mm + hh * 32] = x[(size_t)m * PSZ + k];
            }
        }
        {
            int nn = t & 63, kk4 = t >> 6;
            #pragma unroll
            for (int hh = 0; hh < 2; hh++) {
                int kk = kk4 + hh * 4;
                int k = k0 + kk, n = n0 + nn;
                bool ok = (n < NFREQ);
                Cs[kk][nn] = ok ? g_ctab[(size_t)k * NFREQ + n] : 0.f;
                Ss[kk][nn] = ok ? g_stab[(size_t)k * NFREQ + n] : 0.f;
            }
        }
        __syncthreads();
        #pragma unroll
        for (int kk = 0; kk < 8; kk++) {
            float4 av = *reinterpret_cast<const float4*>(&As[kk][ty * 4]);
            float4 cv = *reinterpret_cast<const float4*>(&Cs[kk][tx * 4]);
            float4 sv = *reinterpret_cast<const float4*>(&Ss[kk][tx * 4]);
            float a[4] = {av.x, av.y, av.z, av.w};
            float cb_[4] = {cv.x, cv.y, cv.z, cv.w};
            float sb_[4] = {sv.x, sv.y, sv.z, sv.w};
            #pragma unroll
            for (int i = 0; i < 4; i++)
                #pragma unroll
                for (int j = 0; j < 4; j++) {
                    ar[i][j] += a[i] * cb_[j];
                    ai[i][j] += a[i] * sb_[j];
                }
        }
        __syncthreads();
    }
    #pragma unroll
    for (int i = 0; i < 4; i++) {
        int m = m0 + ty * 4 + i;
        #pragma unroll
        for (int j = 0; j < 4; j++) {
            int n = n0 + tx * 4 + j;
            if (n < NFREQ) {
                float re = ar[i][j], im = ai[i][j];
                g_spec[(size_t)m * NFREQ + n] = sqrtf(re * re + im * im) * 0.005f;
            }
        }
    }
}

// ---------------------------------------------------------------------------
__global__ __launch_bounds__(256) void k_conv1(const float* __restrict__ x,
                                               const float* __restrict__ w,
                                               const float* __restrict__ bias) {
    int br = blockIdx.x;
    int b = br / RR, r = br % RR;
    __shared__ float xs[248];
    __shared__ float ws[C25 * 49];
    __shared__ float bs[C25];
    int t = threadIdx.x;
    if (t < 248) xs[t] = (t >= 24 && t < 224) ? x[(size_t)br * PSZ + t - 24] : 0.f;
    for (int i = t; i < C25 * 49; i += 256) ws[i] = w[i];
    if (t < C25) bs[t] = bias[t];
    __syncthreads();
    if (t < 200) {
        int oc = t >> 3, ow = t & 7;
        float acc = bs[oc];
        int base = ow * 25;
        #pragma unroll 7
        for (int k = 0; k < 49; k++)
            acc += xs[base + k] * ws[oc * 49 + k];
        g_bufA[(((size_t)b * C25 + oc) * RR + r) * W8 + ow] = acc;
    }
}

// ---------------------------------------------------------------------------
__global__ __launch_bounds__(256) void k_gnstats(const float* __restrict__ h) {
    int bg = blockIdx.x;
    int b = bg / 5, g = bg % 5;
    float s1 = 0.f, s2 = 0.f;
    const int per = RR * W8;
    for (int i = threadIdx.x; i < 5 * per; i += 256) {
        int oc = g * 5 + i / per;
        int rw = i % per;
        float v = h[(size_t)(b * C25 + oc) * per + rw];
        s1 += v; s2 += v * v;
    }
    __shared__ float r1[256], r2[256];
    int t = threadIdx.x;
    r1[t] = s1; r2[t] = s2;
    __syncthreads();
    for (int s = 128; s > 0; s >>= 1) {
        if (t < s) { r1[t] += r1[t + s]; r2[t] += r2[t + s]; }
        __syncthreads();
    }
    if (t == 0) {
        float m = r1[0] / 22800.f;
        float var = r2[0] / 22800.f - m * m;
        g_mean[bg] = m;
        g_rstd[bg] = rsqrtf(var + 1e-5f);
    }
}

// ---------------------------------------------------------------------------
__global__ __launch_bounds__(256) void k_conv3x(const float* __restrict__ in,
                                                const float* __restrict__ w,
                                                const float* __restrict__ bias,
                                                const float* __restrict__ gns,
                                                const float* __restrict__ gnb,
                                                float* __restrict__ out) {
    int bi = blockIdx.x;
    int b = bi / 72, rt = bi % 72;
    int r0 = rt * 8;
    int nrows = min(8, RR - r0);
    __shared__ float sIn[C25][8][W8];
    __shared__ float sW[C25 * C25 * 3];
    __shared__ float sB[C25];
    __shared__ float sMean[C25], sRstd[C25], sSc[C25], sBi[C25];
    int t = threadIdx.x;
    for (int i = t; i < C25 * C25 * 3; i += 256) sW[i] = w[i];
    if (t < C25) {
        sB[t] = bias[t];
        int bg = b * 5 + t / 5;
        sMean[t] = g_mean[bg];
        sRstd[t] = g_rstd[bg];
        sSc[t]   = gns[t];
        sBi[t]   = gnb[t];
    }
    for (int i = t; i < C25 * nrows * W8; i += 256) {
        int ic = i / (nrows * W8);
        int lr = (i / W8) % nrows;
        int ww = i & 7;
        sIn[ic][lr][ww] = in[(((size_t)b * C25 + ic) * RR + r0 + lr) * W8 + ww];
    }
    __syncthreads();
    for (int i = t; i < C25 * nrows * W8; i += 256) {
        int ic = i / (nrows * W8);
        int lr = (i / W8) % nrows;
        int ww = i & 7;
        float v = (sIn[ic][lr][ww] - sMean[ic]) * sRstd[ic] * sSc[ic] + sBi[ic];
        sIn[ic][lr][ww] = gelu_exact(v);
    }
    __syncthreads();
    if (t < 200) {
        int oc = t >> 3, ww = t & 7;
        for (int lr = 0; lr < nrows; lr++) {
            float acc = sB[oc];
            #pragma unroll
            for (int ic = 0; ic < C25; ic++) {
                const float* wp = &sW[(oc * C25 + ic) * 3];
                if (ww > 0) acc += sIn[ic][lr][ww - 1] * wp[0];
                acc += sIn[ic][lr][ww] * wp[1];
                if (ww < 7) acc += sIn[ic][lr][ww + 1] * wp[2];
            }
            out[(((size_t)b * C25 + oc) * RR + r0 + lr) * W8 + ww] = acc;
        }
    }
}

// ---------------------------------------------------------------------------
__global__ __launch_bounds__(256) void k_mkpe(const float* __restrict__ gns,
                                              const float* __restrict__ gnb,
                                              const float* __restrict__ spec_b) {
    int i = blockIdx.x * 256 + threadIdx.x;
    if (i >= PETOT) return;
    int tkn = i / DMD, d = i % DMD;
    int b = tkn / RR, r = tkn % RR;
    int ic = d >> 3;
    int bg = b * 5 + ic / 5;
    float raw = g_bufA[(((size_t)b * C25 + ic) * RR + r) * W8 + (d & 7)];
    float v = (raw - g_mean[bg]) * g_rstd[bg] * gns[ic] + gnb[ic];
    g_pe[i] = gelu_exact(v) + spec_b[d];
}

// ---------------------------------------------------------------------------
__global__ __launch_bounds__(256) void k_sgemm(const float* __restrict__ A,
                                               const float* __restrict__ Bm,
                                               float* __restrict__ C,
                                               int M, int N, int K,
                                               int lda, int bk, int bn, int ldc,
                                               int accFlag) {
    __shared__ __align__(16) float As[8][68];
    __shared__ __align__(16) float Bs[8][68];
    int m0 = blockIdx.y * 64, n0 = blockIdx.x * 64;
    int t = threadIdx.x;
    int tx = t % 16, ty = t / 16;
    float acc[4][4];
    #pragma unroll
    for (int i = 0; i < 4; i++)
        #pragma unroll
        for (int j = 0; j < 4; j++) acc[i][j] = 0.f;

    int nk = (K + 7) / 8;
    for (int kb = 0; kb < nk; kb++) {
        int k0 = kb * 8;
        {
            int kk = t & 7, mm = t >> 3;
            int k = k0 + kk;
            #pragma unroll
            for (int hh = 0; hh < 2; hh++) {
                int m = m0 + mm + hh * 32;
                As[kk][mm + hh * 32] = (k < K && m < M) ? A[(size_t)m * lda + k] : 0.f;
            }
        }
        {
            int kk = t & 7, nn = t >> 3;
            int k = k0 + kk;
            #pragma unroll
            for (int hh = 0; hh < 2; hh++) {
                int n = n0 + nn + hh * 32;
                Bs[kk][nn + hh * 32] = (k < K && n < N) ? Bm[(size_t)k * bk + (size_t)n * bn] : 0.f;
            }
        }
        __syncthreads();
        #pragma unroll
        for (int kk = 0; kk < 8; kk++) {
            float4 av = *reinterpret_cast<const float4*>(&As[kk][ty * 4]);
            float4 bv = *reinterpret_cast<const float4*>(&Bs[kk][tx * 4]);
            float a[4] = {av.x, av.y, av.z, av.w};
            float bb[4] = {bv.x, bv.y, bv.z, bv.w};
            #pragma unroll
            for (int i = 0; i < 4; i++)
                #pragma unroll
                for (int j = 0; j < 4; j++) acc[i][j] += a[i] * bb[j];
        }
        __syncthreads();
    }
    #pragma unroll
    for (int i = 0; i < 4; i++) {
        int m = m0 + ty * 4 + i;
        if (m >= M) continue;
        #pragma unroll
        for (int j = 0; j < 4; j++) {
            int n = n0 + tx * 4 + j;
            if (n < N) {
                size_t o = (size_t)m * ldc + n;
                C[o] = accFlag ? (C[o] + acc[i][j]) : acc[i][j];
            }
        }
    }
}

// ---------------------------------------------------------------------------
__global__ __launch_bounds__(256) void k_c0(const float* __restrict__ cb,
                                            const float* __restrict__ inp_b) {
    int k = blockIdx.x;
    float s = 0.f, sb = 0.f;
    for (int l = threadIdx.x; l < LLM; l += 256) {
        float v = cb[(size_t)k * LLM + l];
        s += v * v;
        sb += inp_b[l] * v;
    }
    __shared__ float r1[256], r2[256];
    int t = threadIdx.x;
    r1[t] = s; r2[t] = sb;
    __syncthreads();
    for (int st = 128; st > 0; st >>= 1) {
        if (t < st) { r1[t] += r1[t + st]; r2[t] += r2[t + st]; }
        __syncthreads();
    }
    if (t == 0) g_c0[k] = 0.5f * r1[0] - r2[0];
}

// ---------------------------------------------------------------------------
// k_prep (R3-identical math) + fused hi-only cvtB into epilogue.
// ---------------------------------------------------------------------------
__global__ __launch_bounds__(256) void k_prep(const float* __restrict__ cb,
                                              const float* __restrict__ inp_w,
                                              const float* __restrict__ outp_w) {
    __shared__ __align__(16) float As[2][8][68];
    __shared__ __align__(16) float B1s[2][8][68];
    __shared__ __align__(16) float B2s[2][8][68];
    const int t = threadIdx.x;
    const int tx = t & 15, ty = t >> 4;
    const int lk = t & 7, lm = t >> 3;
    const int nn = t & 63, kq = t >> 6;
    const int m0 = blockIdx.y * 64, n0 = blockIdx.x * 64;

    unsigned long long a1[4][2], a2[4][2];
    #pragma unroll
    for (int i = 0; i < 4; i++)
        #pragma unroll
        for (int jp = 0; jp < 2; jp++) { a1[i][jp] = 0ULL; a2[i][jp] = 0ULL; }

    #pragma unroll
    for (int h = 0; h < 2; h++) {
        As[0][lk][lm + h * 32] = cb[(size_t)(m0 + lm + h * 32) * LLM + lk];
        int kk = kq + h * 4;
        B1s[0][kk][nn] = (n0 + nn < DMD) ? inp_w[(size_t)kk * DMD + n0 + nn] : 0.f;
        B2s[0][lk][lm + h * 32] = (n0 + lm + h * 32 < DMD)
            ? outp_w[(size_t)(n0 + lm + h * 32) * LLM + lk] : 0.f;
    }
    __syncthreads();
    for (int kb = 0; kb < LLM / 8; kb++) {
        int cur = kb & 1, nxt = cur ^ 1;
        if (kb < LLM / 8 - 1) {
            int k0 = (kb + 1) * 8;
            #pragma unroll
            for (int h = 0; h < 2; h++) {
                As[nxt][lk][lm + h * 32] = cb[(size_t)(m0 + lm + h * 32) * LLM + k0 + lk];
                int kk = kq + h * 4;
                B1s[nxt][kk][nn] = (n0 + nn < DMD) ? inp_w[(size_t)(k0 + kk) * DMD + n0 + nn] : 0.f;
                B2s[nxt][lk][lm + h * 32] = (n0 + lm + h * 32 < DMD)
                    ? outp_w[(size_t)(n0 + lm + h * 32) * LLM + k0 + lk] : 0.f;
            }
        }
        #pragma unroll
        for (int kk = 0; kk < 8; kk++) {
            float4 av = *reinterpret_cast<const float4*>(&As[cur][kk][ty * 4]);
            float4 b1 = *reinterpret_cast<const float4*>(&B1s[cur][kk][tx * 4]);
            float4 b2 = *reinterpret_cast<const float4*>(&B2s[cur][kk][tx * 4]);
            unsigned long long b1p[2], b2p[2];
            PACK2(b1p[0], b1.x, b1.y); PACK2(b1p[1], b1.z, b1.w);
            PACK2(b2p[0], b2.x, b2.y); PACK2(b2p[1], b2.z, b2.w);
            float aa[4] = {av.x, av.y, av.z, av.w};
            #pragma unroll
            for (int i = 0; i < 4; i++) {
                unsigned long long ap;
                PACKDUP(ap, aa[i]);
                FMA2(a1[i][0], ap, b1p[0]);
                FMA2(a1[i][1], ap, b1p[1]);
                FMA2(a2[i][0], ap, b2p[0]);
                FMA2(a2[i][1], ap, b2p[1]);
            }
        }
        __syncthreads();
    }
    #pragma unroll
    for (int i = 0; i < 4; i++) {
        int m = m0 + ty * 4 + i;
        #pragma unroll
        for (int jp = 0; jp < 2; jp++) {
            unsigned lo, hi;
            int n = n0 + tx * 4 + jp * 2;
            UNPK2(lo, hi, a1[i][jp]);
            #pragma unroll
            for (int half = 0; half < 2; half++) {
                int nc = n + half;
                if (nc < DMD) {
                    float v = __uint_as_float(half ? hi : lo);
                    g_G[(size_t)m * DMD + nc] = v;
                    g_B2[(size_t)m * KPAD + nc] = __float2bfloat16(v);
                }
            }
            UNPK2(lo, hi, a2[i][jp]);
            if (n < DMD)     g_cout[(size_t)m * DMD + n]     = __uint_as_float(lo);
            if (n + 1 < DMD) g_cout[(size_t)m * DMD + n + 1] = __uint_as_float(hi);
        }
    }
}

// ---------------------------------------------------------------------------
// Gmax = max_k ||G_k||2 (positive-float bits monotonic -> plain atomicMax).
// One warp per code row.
// ---------------------------------------------------------------------------
__global__ __launch_bounds__(256) void k_gnorm() {
    int wid = threadIdx.x >> 5, lid = threadIdx.x & 31;
    int k = blockIdx.x * 8 + wid;
    if (k >= KCB) return;
    const float* gr = g_G + (size_t)k * DMD;
    float s = 0.f;
    for (int q = lid; q < DMD; q += 32) { float v = gr[q]; s += v * v; }
    for (int o = 16; o; o >>= 1) s += __shfl_xor_sync(0xFFFFFFFFu, s, o);
    if (lid == 0) atomicMax(&g_gmaxu, __float_as_uint(sqrtf(s)));
}

// ||p_t||2 per token (one warp per token).
__global__ __launch_bounds__(256) void k_pnorm() {
    int wid = threadIdx.x >> 5, lid = threadIdx.x & 31;
    int tt = blockIdx.x * 8 + wid;
    if (tt >= TT) return;
    const float* pe = g_bufA + (size_t)tt * DMD;
    float s = 0.f;
    for (int q = lid; q < DMD; q += 32) { float v = pe[q]; s += v * v; }
    for (int o = 16; o; o >>= 1) s += __shfl_xor_sync(0xFFFFFFFFu, s, o);
    if (lid == 0) g_pn[tt] = sqrtf(s);
}

// ---------------------------------------------------------------------------
__global__ __launch_bounds__(256) void k_pos(const float* __restrict__ pw,
                                             const float* __restrict__ pb) {
    int b = blockIdx.x / DMD, d = blockIdx.x % DMD;
    __shared__ float mp[RR];
    __shared__ float w[133];
    int t = threadIdx.x;
    for (int i = t; i < RR; i += 256)
        mp[i] = g_pe[((size_t)b * RR + i) * DMD + d];
    if (t < 133) w[t] = pw[d * 133 + t];
    __syncthreads();
    float bias = pb[d];
    for (int o = t; o < RR; o += 256) {
        int ch = o / NPP, pn = o % NPP;
        float acc = mp[o] + bias;
        #pragma unroll
        for (int i = 0; i < 19; i++) {
            int ci = ch + i - 9;
            if (ci < 0 || ci >= CHN) continue;
            int base = ci * NPP;
            #pragma unroll
            for (int j = 0; j < 7; j++) {
                int pj = pn + j - 3;
                if (pj < 0 || pj >= NPP) continue;
                acc += mp[base + pj] * w[i * 7 + j];
            }
        }
        g_bufA[((size_t)b * RR + o) * DMD + d] = acc;
    }
}

// ---------------------------------------------------------------------------
// hi-only bf16 conversion for A: A2[t][d] = bf16(pe2[t][d]), pad cols zero.
// ---------------------------------------------------------------------------
__global__ __launch_bounds__(256) void k_cvtA() {
    size_t i = (size_t)blockIdx.x * 256 + threadIdx.x;
    if (i >= (size_t)TTP * KPAD) return;
    int t = (int)(i / KPAD), c = (int)(i % KPAD);
    __nv_bfloat16 v = __float2bfloat16(0.f);
    if (t < TT && c < DMD)
        v = __float2bfloat16(g_bufA[(size_t)t * DMD + c]);
    g_A2[i] = v;
}

// ---------------------------------------------------------------------------
// phase1: approx scores via mma.sync m16n8k16 bf16->fp32, ldmatrix loads,
// reg-prefetch pipeline, fp16 store + fp32 rowmin atomics. K' = 256.
// ---------------------------------------------------------------------------
#define SK 72

__device__ __forceinline__ void mma_bf16(float* c, uint32_t a0, uint32_t a1,
                                         uint32_t a2, uint32_t a3,
                                         uint32_t b0, uint32_t b1) {
    asm volatile(
        "mma.sync.aligned.m16n8k16.row.col.f32.bf16.bf16.f32 "
        "{%0,%1,%2,%3}, {%4,%5,%6,%7}, {%8,%9}, {%0,%1,%2,%3};"
        : "+f"(c[0]), "+f"(c[1]), "+f"(c[2]), "+f"(c[3])
        : "r"(a0), "r"(a1), "r"(a2), "r"(a3), "r"(b0), "r"(b1));
}

__device__ __forceinline__ void ldsm4(uint32_t& r0, uint32_t& r1,
                                      uint32_t& r2, uint32_t& r3, uint32_t addr) {
    asm volatile("ldmatrix.sync.aligned.m8n8.x4.shared.b16 {%0,%1,%2,%3}, [%4];"
        : "=r"(r0), "=r"(r1), "=r"(r2), "=r"(r3) : "r"(addr));
}

__global__ __launch_bounds__(256) void k_phase1() {
    __shared__ __nv_bfloat16 As[128][SK];
    __shared__ __nv_bfloat16 Bs[128][SK];
    __shared__ unsigned urmin[128];
    const int t = threadIdx.x, wid = t >> 5, lane = t & 31;
    const int m0 = blockIdx.x * 128, n0 = blockIdx.y * 128;
    const int wm = wid >> 2, wn = wid & 3;
    const int r = lane >> 2, cc = (lane & 3) * 2;
    const int lrow = t >> 3, lq = t & 7;

    if (t < 128) urmin[t] = 0xFFFFFFFFu;

    const int lj = lane >> 3, ri = lane & 7;
    const uint32_t aBase = smem_to_u32(&As[0][0]);
    const uint32_t bBase = smem_to_u32(&Bs[0][0]);
    uint32_t aAddr[4], bAddr[2];
    #pragma unroll
    for (int mt = 0; mt < 4; mt++)
        aAddr[mt] = aBase + (uint32_t)(((wm * 64 + mt * 16 + (lj & 1) * 8 + ri) * SK
                                        + (lj >> 1) * 8) * 2);
    #pragma unroll
    for (int p = 0; p < 2; p++)
        bAddr[p] = bBase + (uint32_t)(((wn * 32 + p * 16 + (lj >> 1) * 8 + ri) * SK
                                       + (lj & 1) * 8) * 2);

    float acc[4][4][4];
    #pragma unroll
    for (int mt = 0; mt < 4; mt++)
        #pragma unroll
        for (int nt = 0; nt < 4; nt++)
            #pragma unroll
            for (int q = 0; q < 4; q++) acc[mt][nt][q] = 0.f;

    float4 pa[4], pb[4];
    #pragma unroll
    for (int s = 0; s < 4; s++) {
        int row = lrow + s * 32;
        pa[s] = *reinterpret_cast<const float4*>(g_A2 + (size_t)(m0 + row) * KPAD + lq * 8);
        pb[s] = *reinterpret_cast<const float4*>(g_B2 + (size_t)(n0 + row) * KPAD + lq * 8);
    }

    for (int ch = 0; ch < NCH; ch++) {
        #pragma unroll
        for (int s = 0; s < 4; s++) {
            int row = lrow + s * 32;
            *reinterpret_cast<float4*>(&As[row][lq * 8]) = pa[s];
            *reinterpret_cast<float4*>(&Bs[row][lq * 8]) = pb[s];
        }
        __syncthreads();
        if (ch < NCH - 1) {
            #pragma unroll
            for (int s = 0; s < 4; s++) {
                int row = lrow + s * 32;
                pa[s] = *reinterpret_cast<const float4*>(
                    g_A2 + (size_t)(m0 + row) * KPAD + (ch + 1) * 64 + lq * 8);
                pb[s] = *reinterpret_cast<const float4*>(
                    g_B2 + (size_t)(n0 + row) * KPAD + (ch + 1) * 64 + lq * 8);
            }
        }
        #pragma unroll
        for (int ks = 0; ks < 4; ks++) {
            const uint32_t koff = (uint32_t)(ks * 16 * 2);
            uint32_t a[4][4], b[4][2];
            #pragma unroll
            for (int mt = 0; mt < 4; mt++)
                ldsm4(a[mt][0], a[mt][1], a[mt][2], a[mt][3], aAddr[mt] + koff);
            #pragma unroll
            for (int p = 0; p < 2; p++)
                ldsm4(b[2 * p][0], b[2 * p][1], b[2 * p + 1][0], b[2 * p + 1][1],
                      bAddr[p] + koff);
            #pragma unroll
            for (int mt = 0; mt < 4; mt++)
                #pragma unroll
                for (int nt = 0; nt < 4; nt++)
                    mma_bf16(acc[mt][nt], a[mt][0], a[mt][1], a[mt][2], a[mt][3],
                             b[nt][0], b[nt][1]);
        }
        __syncthreads();
    }

    #pragma unroll
    for (int mt = 0; mt < 4; mt++) {
        int lr0 = wm * 64 + mt * 16 + r;
        float mlo = INFINITY, mhi = INFINITY;
        #pragma unroll
        for (int nt = 0; nt < 4; nt++) {
            int col = n0 + wn * 32 + nt * 8 + cc;
            float c0a = g_c0[col], c0b = g_c0[col + 1];
            float s0 = c0a - acc[mt][nt][0], s1 = c0b - acc[mt][nt][1];
            float s2 = c0a - acc[mt][nt][2], s3 = c0b - acc[mt][nt][3];
            mlo = fminf(mlo, fminf(s0, s1));
            mhi = fminf(mhi, fminf(s2, s3));
            int row0 = m0 + lr0;
            if (row0 < TT)
                *reinterpret_cast<__half2*>(&g_sap16[(size_t)row0 * KCB + col]) =
                    __floats2half2_rn(s0, s1);
            if (row0 + 8 < TT)
                *reinterpret_cast<__half2*>(&g_sap16[(size_t)(row0 + 8) * KCB + col]) =
                    __floats2half2_rn(s2, s3);
        }
        atomicMin(&urmin[lr0], fenc(mlo));
        atomicMin(&urmin[lr0 + 8], fenc(mhi));
    }
    __syncthreads();
    if (t < 128 && m0 + t < TT)
        atomicMin(&g_rowmin[m0 + t], urmin[t]);
}

// ---------------------------------------------------------------------------
// phase2: thr = rowmin + 2*Cb*||p||*Gmax + 6e-4|rowmin| + 1e-3 (rigorous
// bound incl. bf16-rn dot error, fp32 accum, fp16 storage). Candidates get
// EXACT fp32 sequential rescore -> first-min idx.
// ---------------------------------------------------------------------------
__global__ __launch_bounds__(256) void k_select() {
    __shared__ int lists[8][256];
    int wid = threadIdx.x >> 5, lid = threadIdx.x & 31;
    int tt = blockIdx.x * 8 + wid;
    if (tt >= TT) return;
    const __half2* __restrict__ srow =
        reinterpret_cast<const __half2*>(g_sap16 + (size_t)tt * KCB);
    float rm = fdec(g_rowmin[tt]);
    float gmax = __uint_as_float(g_gmaxu);
    float thr = rm + 8.4e-3f * g_pn[tt] * gmax + 6e-4f * fabsf(rm) + 1e-3f;

    int cnt = 0;
    for (int j = 0; j < 64; j++) {
        int p = j * 32 + lid;
        __half2 h2 = srow[p];
        bool c0 = (__low2float(h2) <= thr);
        bool c1 = (__high2float(h2) <= thr);
        unsigned m0 = __ballot_sync(0xFFFFFFFFu, c0);
        if (c0) {
            int pos = cnt + __popc(m0 & ((1u << lid) - 1u));
            if (pos < 256) lists[wid][pos] = 2 * p;
        }
        cnt += __popc(m0);
        unsigned m1 = __ballot_sync(0xFFFFFFFFu, c1);
        if (c1) {
            int pos = cnt + __popc(m1 & ((1u << lid) - 1u));
            if (pos < 256) lists[wid][pos] = 2 * p + 1;
        }
        cnt += __popc(m1);
    }
    __syncwarp();

    const float* __restrict__ pe = g_bufA + (size_t)tt * DMD;
    float bv = INFINITY; int bk = 0;
    if (cnt <= 256) {
        for (int c = lid; c < cnt; c += 32) {
            int k = lists[wid][c];
            const float* gr = g_G + (size_t)k * DMD;
            float acc = 0.f;
            #pragma unroll 1
            for (int q = 0; q < DMD; q++) acc = fmaf(pe[q], gr[q], acc);
            float s = g_c0[k] - acc;
            if (s < bv || (s == bv && k < bk)) { bv = s; bk = k; }
        }
    } else {
        for (int k = lid; k < KCB; k += 32) {
            const float* gr = g_G + (size_t)k * DMD;
            float acc = 0.f;
            #pragma unroll 1
            for (int q = 0; q < DMD; q++) acc = fmaf(pe[q], gr[q], acc);
            float s = g_c0[k] - acc;
            if (s < bv || (s == bv && k < bk)) { bv = s; bk = k; }
        }
    }
    for (int o = 16; o; o >>= 1) {
        float ov = __shfl_xor_sync(0xFFFFFFFFu, bv, o);
        int ok = __shfl_xor_sync(0xFFFFFFFFu, bk, o);
        if (ov < bv || (ov == bv && ok < bk)) { bv = ov; bk = ok; }
    }
    if (lid == 0) g_idx[tt] = bk;
}

// ---------------------------------------------------------------------------
__global__ __launch_bounds__(256) void k_gather(const float* __restrict__ outp_b,
                                                float* __restrict__ out) {
    int i = blockIdx.x * 256 + threadIdx.x;
    if (i >= PETOT) return;
    int tkn = i / DMD, d = i % DMD;
    out[i] = g_cout[(size_t)g_idx[tkn] * DMD + d] + outp_b[d];
}

// ---------------------------------------------------------------------------
extern "C" void kernel_launch(void* const* d_in, const int* in_sizes, int n_in,
                              void* d_out, int out_size) {
    const float* x      = (const float*)d_in[0];
    const float* c1w    = (const float*)d_in[1];
    const float* c1b    = (const float*)d_in[2];
    const float* gn1s   = (const float*)d_in[3];
    const float* gn1b   = (const float*)d_in[4];
    const float* c2w    = (const float*)d_in[5];
    const float* c2b    = (const float*)d_in[6];
    const float* gn2s   = (const float*)d_in[7];
    const float* gn2b   = (const float*)d_in[8];
    const float* c3w    = (const float*)d_in[9];
    const float* c3b    = (const float*)d_in[10];
    const float* gn3s   = (const float*)d_in[11];
    const float* gn3b   = (const float*)d_in[12];
    const float* spec_w = (const float*)d_in[13];
    const float* spec_b = (const float*)d_in[14];
    const float* pos_w  = (const float*)d_in[15];
    const float* pos_b  = (const float*)d_in[16];
    const float* inp_w  = (const float*)d_in[17];
    const float* inp_b  = (const float*)d_in[18];
    const float* cb     = (const float*)d_in[19];
    const float* outp_w = (const float*)d_in[20];
    const float* outp_b = (const float*)d_in[21];
    float* out = (float*)d_out;

    static cudaStream_t s2 = nullptr, s3 = nullptr;
    static cudaEvent_t evFork = nullptr, evJoin = nullptr, evDft = nullptr;
    if (s2 == nullptr) {
        cudaStreamCreateWithFlags(&s2, cudaStreamNonBlocking);
        cudaStreamCreateWithFlags(&s3, cudaStreamNonBlocking);
        cudaEventCreateWithFlags(&evFork, cudaEventDisableTiming);
        cudaEventCreateWithFlags(&evJoin, cudaEventDisableTiming);
        cudaEventCreateWithFlags(&evDft,  cudaEventDisableTiming);
    }

    float *pSpec, *pBufA, *pBufB, *pPe;
    cudaGetSymbolAddress((void**)&pSpec, g_spec);
    cudaGetSymbolAddress((void**)&pBufA, g_bufA);
    cudaGetSymbolAddress((void**)&pBufB, g_bufB);
    cudaGetSymbolAddress((void**)&pPe,   g_pe);

    const int EW = (HTOT + 255) / 256;

    // ---- fork ----
    cudaEventRecord(evFork, 0);
    cudaStreamWaitEvent(s2, evFork, 0);
    cudaStreamWaitEvent(s3, evFork, 0);

    // s2: codebook branch (prep writes G, cout, B2-hi; then gnorm + c0)
    k_prep<<<dim3(4, 64), 256, 0, s2>>>(cb, inp_w, outp_w);
    k_gnorm<<<KCB / 8, 256, 0, s2>>>();
    k_c0<<<KCB, 256, 0, s2>>>(cb, inp_b);

    // s3: spectral DFT (table + fused re/im/mag GEMM)
    k_twtab<<<(PSZ * NFREQ + 255) / 256, 256, 0, s3>>>();
    k_dftgemm<<<dim3(2, TT / 64), 256, 0, s3>>>(x);
    cudaEventRecord(evDft, s3);

    // main: conv chain
    k_initmin<<<(TT + 255) / 256, 256>>>();
    k_conv1<<<TT, 256>>>(x, c1w, c1b);
    k_gnstats<<<BB * 5, 256>>>(pBufA);
    k_conv3x<<<BB * 72, 256>>>(pBufA, c2w, c2b, gn1s, gn1b, pBufB);
    k_gnstats<<<BB * 5, 256>>>(pBufB);
    k_conv3x<<<BB * 72, 256>>>(pBufB, c3w, c3b, gn2s, gn2b, pBufA);
    k_gnstats<<<BB * 5, 256>>>(pBufA);
    k_mkpe<<<EW, 256>>>(gn3s, gn3b, spec_b);
    cudaStreamWaitEvent(0, evDft, 0);
    k_sgemm<<<dim3((DMD + 63) / 64, TT / 64), 256>>>(pSpec, spec_w, pPe,
        TT, DMD, NFREQ, NFREQ, 1, NFREQ, DMD, 1);
    k_pos<<<BB * DMD, 256>>>(pos_w, pos_b);
    k_pnorm<<<(TT + 7) / 8, 256>>>();
    k_cvtA<<<(int)(((size_t)TTP * KPAD + 255) / 256), 256>>>();

    // ---- join with s2 ----
    cudaEventRecord(evJoin, s2);
    cudaStreamWaitEvent(0, evJoin, 0);

    k_phase1<<<dim3(TTP / 128, KCB / 128), 256>>>();
    k_select<<<(TT + 7) / 8, 256>>>();
    k_gather<<<EW, 256>>>(outp_b, out);
}